// round 1
// baseline (speedup 1.0000x reference)
#include <cuda_runtime.h>
#include <cuda_bf16.h>
#include <math.h>

// Problem dims (fixed by the reference)
#define NTOK 8192
#define CDIM 1024
#define HDIM 128

// Scratch (allocation-free rule: __device__ globals)
__device__ float g_q[(size_t)NTOK * HDIM];            // 4 MB
__device__ float g_k[(size_t)NTOK * HDIM];            // 4 MB
__device__ float g_v[(size_t)NTOK * CDIM];            // 32 MB
__device__ float g_s[(size_t)NTOK * NTOK];            // 256 MB attention matrix
__device__ float g_o[(size_t)NTOK * CDIM];            // 32 MB

// ---------------------------------------------------------------------------
// Generic fp32 GEMM: C = alpha * A @ op(B) + bias
//   A: (M, K) row-major
//   TRANS_B = true : B is (N, K) row-major, C[m,n] = sum_k A[m,k] * B[n,k]
//   TRANS_B = false: B is (K, N) row-major, C[m,n] = sum_k A[m,k] * B[k,n]
// Tile: BM=BN=128, BK=16; 256 threads; 8x8 per-thread microtile.
// All dims must be divisible by the tile sizes (true for every call here).
// ---------------------------------------------------------------------------
template <bool TRANS_B, bool HAS_BIAS>
__global__ __launch_bounds__(256, 2)
void gemm128(const float* __restrict__ A, const float* __restrict__ B,
             const float* __restrict__ bias, float* __restrict__ Cout,
             int M, int Nn, int K, float alpha) {
    constexpr int BM = 128, BN = 128, BK = 16;
    __shared__ float As[BK][BM];
    __shared__ float Bs[BK][BN];

    const int tid  = threadIdx.x;           // 0..255
    const int m0   = blockIdx.y * BM;
    const int n0   = blockIdx.x * BN;
    const int trow = tid >> 4;              // 0..15
    const int tcol = tid & 15;              // 0..15
    const int rowBase = trow * 8;
    const int colBase = tcol * 8;

    float acc[8][8];
#pragma unroll
    for (int i = 0; i < 8; i++)
#pragma unroll
        for (int j = 0; j < 8; j++) acc[i][j] = 0.f;

    for (int k0 = 0; k0 < K; k0 += BK) {
        // ---- Load A tile: BM x BK (512 float4, 2 per thread) ----
#pragma unroll
        for (int t = 0; t < 2; t++) {
            int f4 = tid + t * 256;
            int r  = f4 >> 2;               // 0..127
            int kg = (f4 & 3) * 4;          // 0,4,8,12
            float4 v = *reinterpret_cast<const float4*>(
                &A[(size_t)(m0 + r) * K + k0 + kg]);
            As[kg + 0][r] = v.x;
            As[kg + 1][r] = v.y;
            As[kg + 2][r] = v.z;
            As[kg + 3][r] = v.w;
        }
        // ---- Load B tile ----
        if (TRANS_B) {
#pragma unroll
            for (int t = 0; t < 2; t++) {
                int f4 = tid + t * 256;
                int r  = f4 >> 2;           // n within tile
                int kg = (f4 & 3) * 4;
                float4 v = *reinterpret_cast<const float4*>(
                    &B[(size_t)(n0 + r) * K + k0 + kg]);
                Bs[kg + 0][r] = v.x;
                Bs[kg + 1][r] = v.y;
                Bs[kg + 2][r] = v.z;
                Bs[kg + 3][r] = v.w;
            }
        } else {
#pragma unroll
            for (int t = 0; t < 2; t++) {
                int f4 = tid + t * 256;
                int kk = f4 >> 5;           // 0..15
                int ng = (f4 & 31) * 4;     // 0..124
                float4 v = *reinterpret_cast<const float4*>(
                    &B[(size_t)(k0 + kk) * Nn + n0 + ng]);
                *reinterpret_cast<float4*>(&Bs[kk][ng]) = v;
            }
        }
        __syncthreads();

        // ---- FMA on the tile ----
#pragma unroll
        for (int kk = 0; kk < BK; kk++) {
            float a[8], b[8];
            *reinterpret_cast<float4*>(&a[0]) =
                *reinterpret_cast<const float4*>(&As[kk][rowBase]);
            *reinterpret_cast<float4*>(&a[4]) =
                *reinterpret_cast<const float4*>(&As[kk][rowBase + 4]);
            *reinterpret_cast<float4*>(&b[0]) =
                *reinterpret_cast<const float4*>(&Bs[kk][colBase]);
            *reinterpret_cast<float4*>(&b[4]) =
                *reinterpret_cast<const float4*>(&Bs[kk][colBase + 4]);
#pragma unroll
            for (int i = 0; i < 8; i++)
#pragma unroll
                for (int j = 0; j < 8; j++)
                    acc[i][j] = fmaf(a[i], b[j], acc[i][j]);
        }
        __syncthreads();
    }

    // ---- Epilogue: alpha scale + optional bias ----
#pragma unroll
    for (int i = 0; i < 8; i++) {
        size_t rowOff = (size_t)(m0 + rowBase + i) * Nn + n0 + colBase;
#pragma unroll
        for (int j = 0; j < 8; j++) {
            float r = acc[i][j] * alpha;
            if (HAS_BIAS) r += bias[n0 + colBase + j];
            Cout[rowOff + j] = r;
        }
    }
}

// ---------------------------------------------------------------------------
// Row softmax over 8192-wide rows, in place. One block (256 thr) per row,
// 32 elements per thread kept in registers (single global read + write).
// ---------------------------------------------------------------------------
__global__ __launch_bounds__(256)
void softmax_rows(float* __restrict__ S) {
    const int row = blockIdx.x;
    float* p = S + (size_t)row * NTOK;
    const int tid = threadIdx.x;

    float vals[32];
    float m = -INFINITY;
#pragma unroll
    for (int i = 0; i < 32; i++) {
        vals[i] = p[tid + i * 256];
        m = fmaxf(m, vals[i]);
    }

    __shared__ float red[256];
    red[tid] = m;
    __syncthreads();
#pragma unroll
    for (int s = 128; s > 0; s >>= 1) {
        if (tid < s) red[tid] = fmaxf(red[tid], red[tid + s]);
        __syncthreads();
    }
    m = red[0];
    __syncthreads();

    float sum = 0.f;
#pragma unroll
    for (int i = 0; i < 32; i++) {
        vals[i] = __expf(vals[i] - m);
        sum += vals[i];
    }
    red[tid] = sum;
    __syncthreads();
#pragma unroll
    for (int s = 128; s > 0; s >>= 1) {
        if (tid < s) red[tid] += red[tid + s];
        __syncthreads();
    }
    sum = red[0];

    float inv = 1.f / sum;
#pragma unroll
    for (int i = 0; i < 32; i++) p[tid + i * 256] = vals[i] * inv;
}

// ---------------------------------------------------------------------------
extern "C" void kernel_launch(void* const* d_in, const int* in_sizes, int n_in,
                              void* d_out, int out_size) {
    const float* x  = (const float*)d_in[0];
    const float* Wq = (const float*)d_in[1];
    const float* bq = (const float*)d_in[2];
    const float* Wk = (const float*)d_in[3];
    const float* bk = (const float*)d_in[4];
    const float* Wv = (const float*)d_in[5];
    const float* bv = (const float*)d_in[6];
    const float* Wo = (const float*)d_in[7];
    const float* bo = (const float*)d_in[8];
    float* out = (float*)d_out;

    float *qp, *kp, *vp, *sp, *op;
    cudaGetSymbolAddress((void**)&qp, g_q);
    cudaGetSymbolAddress((void**)&kp, g_k);
    cudaGetSymbolAddress((void**)&vp, g_v);
    cudaGetSymbolAddress((void**)&sp, g_s);
    cudaGetSymbolAddress((void**)&op, g_o);

    const float scale = 1.0f / sqrtf((float)HDIM);
    dim3 blk(256);

    // q = x @ Wq.T + bq   (8192 x 128)
    gemm128<true, true><<<dim3(HDIM / 128, NTOK / 128), blk>>>(
        x, Wq, bq, qp, NTOK, HDIM, CDIM, 1.0f);
    // k = x @ Wk.T + bk   (8192 x 128)
    gemm128<true, true><<<dim3(HDIM / 128, NTOK / 128), blk>>>(
        x, Wk, bk, kp, NTOK, HDIM, CDIM, 1.0f);
    // v = x @ Wv.T + bv   (8192 x 1024)
    gemm128<true, true><<<dim3(CDIM / 128, NTOK / 128), blk>>>(
        x, Wv, bv, vp, NTOK, CDIM, CDIM, 1.0f);

    // scores = (q @ k.T) * scale   (8192 x 8192)
    gemm128<true, false><<<dim3(NTOK / 128, NTOK / 128), blk>>>(
        qp, kp, nullptr, sp, NTOK, NTOK, HDIM, scale);

    // softmax rows, in place
    softmax_rows<<<NTOK, blk>>>(sp);

    // o = attn @ v   (8192 x 1024), NN form
    gemm128<false, false><<<dim3(CDIM / 128, NTOK / 128), blk>>>(
        sp, vp, nullptr, op, NTOK, CDIM, NTOK, 1.0f);

    // out = o @ Wo.T + bo   (8192 x 1024)
    gemm128<true, true><<<dim3(CDIM / 128, NTOK / 128), blk>>>(
        op, Wo, bo, out, NTOK, CDIM, CDIM, 1.0f);
}

// round 3
// speedup vs baseline: 3.5659x; 3.5659x over previous
#include <cuda_runtime.h>
#include <math.h>
#include <cstdint>

#define NTOK 8192
#define CDIM 1024
#define HDIM 128

// Scratch (__device__ globals; allocation-free rule)
__device__ float g_q [(size_t)NTOK * HDIM];
__device__ float g_k [(size_t)NTOK * HDIM];
__device__ float g_vT[(size_t)CDIM * NTOK];   // v transposed: [C, N]
__device__ float g_s [(size_t)NTOK * NTOK];   // 256 MB scores
__device__ float g_o [(size_t)NTOK * CDIM];

// ---------------- portable PTX helpers (sm_80-level only) ----------------
__device__ __forceinline__ uint32_t smem_u32(const void* p) {
    uint32_t a;
    asm("{ .reg .u64 t; cvta.to.shared.u64 t, %1; cvt.u32.u64 %0, t; }"
        : "=r"(a) : "l"(p));
    return a;
}
__device__ __forceinline__ void cp16(uint32_t s, const void* g) {
    asm volatile("cp.async.cg.shared.global [%0], [%1], 16;" :: "r"(s), "l"(g));
}
__device__ __forceinline__ uint32_t f2tf(uint32_t rawbits) {
    uint32_t u;
    asm("cvt.rna.tf32.f32 %0, %1;" : "=r"(u) : "f"(__uint_as_float(rawbits)));
    return u;
}
__device__ __forceinline__ void ldsm4(uint32_t& r0, uint32_t& r1,
                                      uint32_t& r2, uint32_t& r3, uint32_t a) {
    asm volatile("ldmatrix.sync.aligned.m8n8.x4.shared.b16 {%0,%1,%2,%3}, [%4];"
                 : "=r"(r0), "=r"(r1), "=r"(r2), "=r"(r3) : "r"(a));
}
__device__ __forceinline__ void mma8(float* c, const uint32_t* a, const uint32_t* b) {
    asm volatile(
        "mma.sync.aligned.m16n8k8.row.col.f32.tf32.tf32.f32 "
        "{%0,%1,%2,%3}, {%4,%5,%6,%7}, {%8,%9}, {%0,%1,%2,%3};"
        : "+f"(c[0]), "+f"(c[1]), "+f"(c[2]), "+f"(c[3])
        : "r"(a[0]), "r"(a[1]), "r"(a[2]), "r"(a[3]), "r"(b[0]), "r"(b[1]));
}

// ---------------------------------------------------------------------------
// tf32 tensor-core GEMM: C[M,Nn] = alpha * A @ B^T (+ bias)
//   A: (M,K) row-major, B: (Nn,K) row-major (both K-major -> NT form)
//   CTA tile 128x128, BK=32. 8 warps as 2(M) x 4(N); warp tile 64x32.
//   Per warp: 4x4 m16n8k8 tiles, 4 k-steps per chunk.
//   SMEM rows padded to 36 floats -> conflict-free ldmatrix.
//   BIAS: 0 none, 1 bias[n], 2 bias[m]
// ---------------------------------------------------------------------------
#define AST 36                       // padded row stride (floats)
#define TILEB (128 * AST * 4)        // one tile, bytes
#define BUFB  (2 * TILEB)            // one double-buffer step (A+B tiles)

template <int BIAS>
__global__ __launch_bounds__(256, 2)
void gemm_mma(const float* __restrict__ A, const float* __restrict__ B,
              const float* __restrict__ bias, float* __restrict__ C,
              int M, int Nn, int K, float alpha) {
    extern __shared__ float sm[];
    const uint32_t sA = smem_u32(sm);            // As[buf] at sA + buf*BUFB
    const uint32_t sB = sA + TILEB;              // Bs[buf] at sB + buf*BUFB

    const int tid = threadIdx.x;
    const int lane = tid & 31, wid = tid >> 5;
    const int wm = wid >> 2, wn = wid & 3;       // warp grid 2x4
    const int m0 = blockIdx.y * 128, n0 = blockIdx.x * 128;

    // ---- ldmatrix source addresses (per-lane), buffer 0, k-step 0 ----
    const int q = lane & 7, sub = lane >> 3;
    uint32_t aAddr[4], bAddr[2];
#pragma unroll
    for (int mt = 0; mt < 4; mt++) {
        int row = wm * 64 + mt * 16 + (sub & 1) * 8 + q;
        int col = (sub >> 1) * 4;
        aAddr[mt] = sA + (uint32_t)(row * AST + col) * 4;
    }
#pragma unroll
    for (int p = 0; p < 2; p++) {
        int row = wn * 32 + p * 16 + (sub >> 1) * 8 + q;
        int col = (sub & 1) * 4;
        bAddr[p] = sB + (uint32_t)(row * AST + col) * 4;
    }

    // ---- cp.async tile loader: chunk c (32 floats of K) -> buffer b ----
    auto load = [&](int c, int b) {
        const uint32_t aBase = sA + (uint32_t)b * BUFB;
        const uint32_t bBase = sB + (uint32_t)b * BUFB;
#pragma unroll
        for (int it = 0; it < 8; it++) {
            int i = tid + it * 256;
            bool isA = i < 1024;
            int idx = i & 1023;
            int rr = idx >> 3, cc = idx & 7;
            const float* g = (isA ? A : B) +
                (size_t)((isA ? m0 : n0) + rr) * K + c * 32 + cc * 4;
            cp16((isA ? aBase : bBase) + (uint32_t)(rr * AST + cc * 4) * 4, g);
        }
        asm volatile("cp.async.commit_group;" ::: "memory");
    };

    const int NC = K >> 5;
    load(0, 0);
    load(1, 1);

    float acc[4][4][4];
#pragma unroll
    for (int i = 0; i < 4; i++)
#pragma unroll
        for (int j = 0; j < 4; j++)
#pragma unroll
            for (int r = 0; r < 4; r++) acc[i][j][r] = 0.f;

    for (int c = 0; c < NC; c++) {
        if (c + 1 < NC) asm volatile("cp.async.wait_group 1;" ::: "memory");
        else            asm volatile("cp.async.wait_group 0;" ::: "memory");
        __syncthreads();

        const uint32_t boff = (uint32_t)(c & 1) * BUFB;
#pragma unroll
        for (int ks = 0; ks < 4; ks++) {
            uint32_t af[4][4], bf[4][2];
#pragma unroll
            for (int mt = 0; mt < 4; mt++) {
                uint32_t r0, r1, r2, r3;
                ldsm4(r0, r1, r2, r3, aAddr[mt] + boff + ks * 32);
                af[mt][0] = f2tf(r0); af[mt][1] = f2tf(r1);
                af[mt][2] = f2tf(r2); af[mt][3] = f2tf(r3);
            }
#pragma unroll
            for (int p = 0; p < 2; p++) {
                uint32_t r0, r1, r2, r3;
                ldsm4(r0, r1, r2, r3, bAddr[p] + boff + ks * 32);
                bf[p * 2 + 0][0] = f2tf(r0); bf[p * 2 + 0][1] = f2tf(r1);
                bf[p * 2 + 1][0] = f2tf(r2); bf[p * 2 + 1][1] = f2tf(r3);
            }
#pragma unroll
            for (int mt = 0; mt < 4; mt++)
#pragma unroll
                for (int nt = 0; nt < 4; nt++)
                    mma8(acc[mt][nt], af[mt], bf[nt]);
        }
        __syncthreads();
        if (c + 2 < NC) load(c + 2, c & 1);
    }

    // ---- epilogue ----
    const int g = lane >> 2, tig = lane & 3;
#pragma unroll
    for (int mt = 0; mt < 4; mt++) {
        const int mrow = m0 + wm * 64 + mt * 16 + g;
        float bR0 = 0.f, bR1 = 0.f;
        if (BIAS == 2) { bR0 = bias[mrow]; bR1 = bias[mrow + 8]; }
#pragma unroll
        for (int nt = 0; nt < 4; nt++) {
            const int ncol = n0 + wn * 32 + nt * 8 + tig * 2;
            float* cc = acc[mt][nt];
            float2 v0, v1;
            v0.x = cc[0] * alpha; v0.y = cc[1] * alpha;
            v1.x = cc[2] * alpha; v1.y = cc[3] * alpha;
            if (BIAS == 1) {
                float b0 = bias[ncol], b1 = bias[ncol + 1];
                v0.x += b0; v0.y += b1; v1.x += b0; v1.y += b1;
            } else if (BIAS == 2) {
                v0.x += bR0; v0.y += bR0; v1.x += bR1; v1.y += bR1;
            }
            *reinterpret_cast<float2*>(&C[(size_t)mrow * Nn + ncol]) = v0;
            *reinterpret_cast<float2*>(&C[(size_t)(mrow + 8) * Nn + ncol]) = v1;
        }
    }
}

// ---------------------------------------------------------------------------
// Row softmax (8192-wide), in place, float4-vectorized. 256 thr/row.
// ---------------------------------------------------------------------------
__global__ __launch_bounds__(256)
void softmax_rows(float* __restrict__ S) {
    const size_t row = blockIdx.x;
    float4* p = reinterpret_cast<float4*>(S + row * NTOK);
    const int tid = threadIdx.x;
    const int lane = tid & 31, wid = tid >> 5;
    __shared__ float red[8];

    float4 v[8];
    float mx = -INFINITY;
#pragma unroll
    for (int i = 0; i < 8; i++) {
        v[i] = p[tid + i * 256];
        mx = fmaxf(mx, fmaxf(fmaxf(v[i].x, v[i].y), fmaxf(v[i].z, v[i].w)));
    }
#pragma unroll
    for (int o = 16; o > 0; o >>= 1) mx = fmaxf(mx, __shfl_xor_sync(~0u, mx, o));
    if (lane == 0) red[wid] = mx;
    __syncthreads();
    mx = red[0];
#pragma unroll
    for (int i = 1; i < 8; i++) mx = fmaxf(mx, red[i]);
    __syncthreads();

    float sum = 0.f;
#pragma unroll
    for (int i = 0; i < 8; i++) {
        v[i].x = __expf(v[i].x - mx); v[i].y = __expf(v[i].y - mx);
        v[i].z = __expf(v[i].z - mx); v[i].w = __expf(v[i].w - mx);
        sum += (v[i].x + v[i].y) + (v[i].z + v[i].w);
    }
#pragma unroll
    for (int o = 16; o > 0; o >>= 1) sum += __shfl_xor_sync(~0u, sum, o);
    if (lane == 0) red[wid] = sum;
    __syncthreads();
    sum = red[0];
#pragma unroll
    for (int i = 1; i < 8; i++) sum += red[i];

    const float inv = 1.f / sum;
#pragma unroll
    for (int i = 0; i < 8; i++) {
        v[i].x *= inv; v[i].y *= inv; v[i].z *= inv; v[i].w *= inv;
        p[tid + i * 256] = v[i];
    }
}

// ---------------------------------------------------------------------------
extern "C" void kernel_launch(void* const* d_in, const int* in_sizes, int n_in,
                              void* d_out, int out_size) {
    const float* x  = (const float*)d_in[0];
    const float* Wq = (const float*)d_in[1];
    const float* bq = (const float*)d_in[2];
    const float* Wk = (const float*)d_in[3];
    const float* bk = (const float*)d_in[4];
    const float* Wv = (const float*)d_in[5];
    const float* bv = (const float*)d_in[6];
    const float* Wo = (const float*)d_in[7];
    const float* bo = (const float*)d_in[8];
    float* out = (float*)d_out;

    float *qp, *kp, *vTp, *sp, *op;
    cudaGetSymbolAddress((void**)&qp,  g_q);
    cudaGetSymbolAddress((void**)&kp,  g_k);
    cudaGetSymbolAddress((void**)&vTp, g_vT);
    cudaGetSymbolAddress((void**)&sp,  g_s);
    cudaGetSymbolAddress((void**)&op,  g_o);

    const float scale = 1.0f / sqrtf((float)HDIM);
    const int SMEM = 2 * BUFB;   // 73728 B

    static bool attr_done = false;
    if (!attr_done) {
        cudaFuncSetAttribute(gemm_mma<0>, cudaFuncAttributeMaxDynamicSharedMemorySize, SMEM);
        cudaFuncSetAttribute(gemm_mma<1>, cudaFuncAttributeMaxDynamicSharedMemorySize, SMEM);
        cudaFuncSetAttribute(gemm_mma<2>, cudaFuncAttributeMaxDynamicSharedMemorySize, SMEM);
        attr_done = true;
    }

    dim3 blk(256);

    // q = x @ Wq.T + bq : M=8192, N=128, K=1024
    gemm_mma<1><<<dim3(1, 64), blk, SMEM>>>(x, Wq, bq, qp, NTOK, HDIM, CDIM, 1.0f);
    // k = x @ Wk.T + bk
    gemm_mma<1><<<dim3(1, 64), blk, SMEM>>>(x, Wk, bk, kp, NTOK, HDIM, CDIM, 1.0f);
    // vT = Wv @ x.T + bv[m] : M=1024 (channels), N=8192 (tokens), K=1024
    gemm_mma<2><<<dim3(64, 8), blk, SMEM>>>(Wv, x, bv, vTp, CDIM, NTOK, CDIM, 1.0f);

    // scores = (q @ k.T) * scale : M=N=8192, K=128
    gemm_mma<0><<<dim3(64, 64), blk, SMEM>>>(qp, kp, nullptr, sp, NTOK, NTOK, HDIM, scale);

    softmax_rows<<<NTOK, blk>>>(sp);

    // o = attn @ vT.T : M=8192, N=1024, K=8192
    gemm_mma<0><<<dim3(8, 64), blk, SMEM>>>(sp, vTp, nullptr, op, NTOK, CDIM, NTOK, 1.0f);

    // out = o @ Wo.T + bo : M=8192, N=1024, K=1024
    gemm_mma<1><<<dim3(8, 64), blk, SMEM>>>(op, Wo, bo, out, NTOK, CDIM, CDIM, 1.0f);
}

// round 4
// speedup vs baseline: 3.7889x; 1.0625x over previous
#include <cuda_runtime.h>
#include <math.h>
#include <cstdint>

#define NTOK 8192
#define CDIM 1024
#define HDIM 128

// Scratch (__device__ globals; allocation-free rule)
__device__ float g_q [(size_t)NTOK * HDIM];
__device__ float g_k [(size_t)NTOK * HDIM];
__device__ float g_vT[(size_t)CDIM * NTOK];   // v transposed: [C, N]
__device__ float g_s [(size_t)NTOK * NTOK];   // 256 MB scores
__device__ float g_o [(size_t)NTOK * CDIM];
__device__ float g_xr[(size_t)NTOK * CDIM];   // tf32-rounded x
__device__ float g_wq[(size_t)HDIM * CDIM];
__device__ float g_wk[(size_t)HDIM * CDIM];
__device__ float g_wv[(size_t)CDIM * CDIM];
__device__ float g_wo[(size_t)CDIM * CDIM];

// ---------------- portable PTX helpers (sm_80-level only) ----------------
__device__ __forceinline__ uint32_t smem_u32(const void* p) {
    uint32_t a;
    asm("{ .reg .u64 t; cvta.to.shared.u64 t, %1; cvt.u32.u64 %0, t; }"
        : "=r"(a) : "l"(p));
    return a;
}
__device__ __forceinline__ void cp16(uint32_t s, const void* g) {
    asm volatile("cp.async.cg.shared.global [%0], [%1], 16;" :: "r"(s), "l"(g));
}
__device__ __forceinline__ float rtf(float x) {   // round-to-nearest tf32
    uint32_t u;
    asm("cvt.rna.tf32.f32 %0, %1;" : "=r"(u) : "f"(x));
    return __uint_as_float(u);
}
__device__ __forceinline__ void ldsm4(uint32_t& r0, uint32_t& r1,
                                      uint32_t& r2, uint32_t& r3, uint32_t a) {
    asm volatile("ldmatrix.sync.aligned.m8n8.x4.shared.b16 {%0,%1,%2,%3}, [%4];"
                 : "=r"(r0), "=r"(r1), "=r"(r2), "=r"(r3) : "r"(a));
}
__device__ __forceinline__ void mma8(float* c, const uint32_t* a, const uint32_t* b) {
    asm volatile(
        "mma.sync.aligned.m16n8k8.row.col.f32.tf32.tf32.f32 "
        "{%0,%1,%2,%3}, {%4,%5,%6,%7}, {%8,%9}, {%0,%1,%2,%3};"
        : "+f"(c[0]), "+f"(c[1]), "+f"(c[2]), "+f"(c[3])
        : "r"(a[0]), "r"(a[1]), "r"(a[2]), "r"(a[3]), "r"(b[0]), "r"(b[1]));
}

// ---------------------------------------------------------------------------
// Rounding pass: dst = tf32_rna(src), float4-vectorized.
// ---------------------------------------------------------------------------
__global__ __launch_bounds__(256)
void round_tf32(const float* __restrict__ src, float* __restrict__ dst, int n4) {
    int i = blockIdx.x * 256 + threadIdx.x;
    if (i < n4) {
        float4 v = reinterpret_cast<const float4*>(src)[i];
        v.x = rtf(v.x); v.y = rtf(v.y); v.z = rtf(v.z); v.w = rtf(v.w);
        reinterpret_cast<float4*>(dst)[i] = v;
    }
}

// ---------------------------------------------------------------------------
// tf32 tensor-core GEMM: C[M,Nn] = alpha * A @ B^T (+ bias)
//   Operands MUST be pre-rounded to tf32 (HW truncation is then exact).
//   CTA tile 128x128, BK=32, 3-stage cp.async pipeline.
//   8 warps as 2(M) x 4(N); warp tile 64x32; 4x4 m16n8k8 tiles, 4 ksteps.
//   SMEM rows padded to 36 floats -> conflict-free ldmatrix.
//   BIAS: 0 none, 1 bias[n], 2 bias[m].  ROUND: round C to tf32 on store.
// ---------------------------------------------------------------------------
#define AST 36                       // padded row stride (floats)
#define TILEB (128 * AST * 4)        // one tile, bytes (18432)
#define BUFB  (2 * TILEB)            // one pipeline stage (A+B tiles)
#define NSTAGE 3

template <int BIAS, int ROUND>
__global__ __launch_bounds__(256, 2)
void gemm_mma(const float* __restrict__ A, const float* __restrict__ B,
              const float* __restrict__ bias, float* __restrict__ C,
              int M, int Nn, int K, float alpha) {
    extern __shared__ float sm[];
    const uint32_t sA = smem_u32(sm);
    const uint32_t sB = sA + TILEB;

    const int tid = threadIdx.x;
    const int lane = tid & 31, wid = tid >> 5;
    const int wm = wid >> 2, wn = wid & 3;       // warp grid 2x4
    const int m0 = blockIdx.y * 128, n0 = blockIdx.x * 128;

    // ---- ldmatrix source addresses (per-lane), stage 0, k-step 0 ----
    const int q = lane & 7, sub = lane >> 3;
    uint32_t aAddr[4], bAddr[2];
#pragma unroll
    for (int mt = 0; mt < 4; mt++) {
        int row = wm * 64 + mt * 16 + (sub & 1) * 8 + q;
        int col = (sub >> 1) * 4;
        aAddr[mt] = sA + (uint32_t)(row * AST + col) * 4;
    }
#pragma unroll
    for (int p = 0; p < 2; p++) {
        int row = wn * 32 + p * 16 + (sub >> 1) * 8 + q;
        int col = (sub & 1) * 4;
        bAddr[p] = sB + (uint32_t)(row * AST + col) * 4;
    }

    const int NC = K >> 5;

    // ---- cp.async loader: chunk c -> stage b. Always commits (maybe empty).
    auto load = [&](int c, int b) {
        if (c < NC) {
            const uint32_t aBase = sA + (uint32_t)b * BUFB;
            const uint32_t bBase = sB + (uint32_t)b * BUFB;
#pragma unroll
            for (int it = 0; it < 8; it++) {
                int i = tid + it * 256;
                bool isA = i < 1024;
                int idx = i & 1023;
                int rr = idx >> 3, cc = idx & 7;
                const float* g = (isA ? A : B) +
                    (size_t)((isA ? m0 : n0) + rr) * K + c * 32 + cc * 4;
                cp16((isA ? aBase : bBase) + (uint32_t)(rr * AST + cc * 4) * 4, g);
            }
        }
        asm volatile("cp.async.commit_group;" ::: "memory");
    };

    load(0, 0);
    load(1, 1);
    load(2, 2);

    float acc[4][4][4];
#pragma unroll
    for (int i = 0; i < 4; i++)
#pragma unroll
        for (int j = 0; j < 4; j++)
#pragma unroll
            for (int r = 0; r < 4; r++) acc[i][j][r] = 0.f;

    for (int c = 0; c < NC; c++) {
        asm volatile("cp.async.wait_group %0;" :: "n"(NSTAGE - 1) : "memory");
        __syncthreads();

        const uint32_t boff = (uint32_t)(c % NSTAGE) * BUFB;
#pragma unroll
        for (int ks = 0; ks < 4; ks++) {
            uint32_t af[4][4], bf[4][2];
#pragma unroll
            for (int mt = 0; mt < 4; mt++)
                ldsm4(af[mt][0], af[mt][1], af[mt][2], af[mt][3],
                      aAddr[mt] + boff + ks * 32);
#pragma unroll
            for (int p = 0; p < 2; p++) {
                uint32_t r0, r1, r2, r3;
                ldsm4(r0, r1, r2, r3, bAddr[p] + boff + ks * 32);
                bf[p * 2 + 0][0] = r0; bf[p * 2 + 0][1] = r1;
                bf[p * 2 + 1][0] = r2; bf[p * 2 + 1][1] = r3;
            }
#pragma unroll
            for (int mt = 0; mt < 4; mt++)
#pragma unroll
                for (int nt = 0; nt < 4; nt++)
                    mma8(acc[mt][nt], af[mt], bf[nt]);
        }
        __syncthreads();
        load(c + NSTAGE, c % NSTAGE);
    }

    // ---- epilogue ----
    const int g = lane >> 2, tig = lane & 3;
#pragma unroll
    for (int mt = 0; mt < 4; mt++) {
        const int mrow = m0 + wm * 64 + mt * 16 + g;
        float bR0 = 0.f, bR1 = 0.f;
        if (BIAS == 2) { bR0 = bias[mrow]; bR1 = bias[mrow + 8]; }
#pragma unroll
        for (int nt = 0; nt < 4; nt++) {
            const int ncol = n0 + wn * 32 + nt * 8 + tig * 2;
            float* cc = acc[mt][nt];
            float2 v0, v1;
            v0.x = cc[0] * alpha; v0.y = cc[1] * alpha;
            v1.x = cc[2] * alpha; v1.y = cc[3] * alpha;
            if (BIAS == 1) {
                float b0 = bias[ncol], b1 = bias[ncol + 1];
                v0.x += b0; v0.y += b1; v1.x += b0; v1.y += b1;
            } else if (BIAS == 2) {
                v0.x += bR0; v0.y += bR0; v1.x += bR1; v1.y += bR1;
            }
            if (ROUND) {
                v0.x = rtf(v0.x); v0.y = rtf(v0.y);
                v1.x = rtf(v1.x); v1.y = rtf(v1.y);
            }
            *reinterpret_cast<float2*>(&C[(size_t)mrow * Nn + ncol]) = v0;
            *reinterpret_cast<float2*>(&C[(size_t)(mrow + 8) * Nn + ncol]) = v1;
        }
    }
}

// ---------------------------------------------------------------------------
// Row softmax (8192-wide), in place, float4-vectorized; output tf32-rounded.
// ---------------------------------------------------------------------------
__global__ __launch_bounds__(256)
void softmax_rows(float* __restrict__ S) {
    const size_t row = blockIdx.x;
    float4* p = reinterpret_cast<float4*>(S + row * NTOK);
    const int tid = threadIdx.x;
    const int lane = tid & 31, wid = tid >> 5;
    __shared__ float red[8];

    float4 v[8];
    float mx = -INFINITY;
#pragma unroll
    for (int i = 0; i < 8; i++) {
        v[i] = p[tid + i * 256];
        mx = fmaxf(mx, fmaxf(fmaxf(v[i].x, v[i].y), fmaxf(v[i].z, v[i].w)));
    }
#pragma unroll
    for (int o = 16; o > 0; o >>= 1) mx = fmaxf(mx, __shfl_xor_sync(~0u, mx, o));
    if (lane == 0) red[wid] = mx;
    __syncthreads();
    mx = red[0];
#pragma unroll
    for (int i = 1; i < 8; i++) mx = fmaxf(mx, red[i]);
    __syncthreads();

    float sum = 0.f;
#pragma unroll
    for (int i = 0; i < 8; i++) {
        v[i].x = __expf(v[i].x - mx); v[i].y = __expf(v[i].y - mx);
        v[i].z = __expf(v[i].z - mx); v[i].w = __expf(v[i].w - mx);
        sum += (v[i].x + v[i].y) + (v[i].z + v[i].w);
    }
#pragma unroll
    for (int o = 16; o > 0; o >>= 1) sum += __shfl_xor_sync(~0u, sum, o);
    if (lane == 0) red[wid] = sum;
    __syncthreads();
    sum = red[0];
#pragma unroll
    for (int i = 1; i < 8; i++) sum += red[i];

    const float inv = 1.f / sum;
#pragma unroll
    for (int i = 0; i < 8; i++) {
        v[i].x = rtf(v[i].x * inv); v[i].y = rtf(v[i].y * inv);
        v[i].z = rtf(v[i].z * inv); v[i].w = rtf(v[i].w * inv);
        p[tid + i * 256] = v[i];
    }
}

// ---------------------------------------------------------------------------
extern "C" void kernel_launch(void* const* d_in, const int* in_sizes, int n_in,
                              void* d_out, int out_size) {
    const float* x  = (const float*)d_in[0];
    const float* Wq = (const float*)d_in[1];
    const float* bq = (const float*)d_in[2];
    const float* Wk = (const float*)d_in[3];
    const float* bk = (const float*)d_in[4];
    const float* Wv = (const float*)d_in[5];
    const float* bv = (const float*)d_in[6];
    const float* Wo = (const float*)d_in[7];
    const float* bo = (const float*)d_in[8];
    float* out = (float*)d_out;

    float *qp, *kp, *vTp, *sp, *op, *xr, *wq, *wk, *wv, *wo;
    cudaGetSymbolAddress((void**)&qp,  g_q);
    cudaGetSymbolAddress((void**)&kp,  g_k);
    cudaGetSymbolAddress((void**)&vTp, g_vT);
    cudaGetSymbolAddress((void**)&sp,  g_s);
    cudaGetSymbolAddress((void**)&op,  g_o);
    cudaGetSymbolAddress((void**)&xr,  g_xr);
    cudaGetSymbolAddress((void**)&wq,  g_wq);
    cudaGetSymbolAddress((void**)&wk,  g_wk);
    cudaGetSymbolAddress((void**)&wv,  g_wv);
    cudaGetSymbolAddress((void**)&wo,  g_wo);

    const float scale = 1.0f / sqrtf((float)HDIM);
    const int SMEM = NSTAGE * BUFB;   // 110592 B

    cudaFuncSetAttribute(gemm_mma<1, 1>, cudaFuncAttributeMaxDynamicSharedMemorySize, SMEM);
    cudaFuncSetAttribute(gemm_mma<2, 1>, cudaFuncAttributeMaxDynamicSharedMemorySize, SMEM);
    cudaFuncSetAttribute(gemm_mma<0, 0>, cudaFuncAttributeMaxDynamicSharedMemorySize, SMEM);
    cudaFuncSetAttribute(gemm_mma<0, 1>, cudaFuncAttributeMaxDynamicSharedMemorySize, SMEM);
    cudaFuncSetAttribute(gemm_mma<1, 0>, cudaFuncAttributeMaxDynamicSharedMemorySize, SMEM);

    dim3 blk(256);

    // ---- pre-round all mainloop operand sources to tf32 ----
    round_tf32<<<(NTOK * CDIM / 4 + 255) / 256, blk>>>(x,  xr, NTOK * CDIM / 4);
    round_tf32<<<(HDIM * CDIM / 4 + 255) / 256, blk>>>(Wq, wq, HDIM * CDIM / 4);
    round_tf32<<<(HDIM * CDIM / 4 + 255) / 256, blk>>>(Wk, wk, HDIM * CDIM / 4);
    round_tf32<<<(CDIM * CDIM / 4 + 255) / 256, blk>>>(Wv, wv, CDIM * CDIM / 4);
    round_tf32<<<(CDIM * CDIM / 4 + 255) / 256, blk>>>(Wo, wo, CDIM * CDIM / 4);

    // q = x @ Wq.T + bq : M=8192, N=128, K=1024  (output tf32-rounded)
    gemm_mma<1, 1><<<dim3(1, 64), blk, SMEM>>>(xr, wq, bq, qp, NTOK, HDIM, CDIM, 1.0f);
    // k = x @ Wk.T + bk
    gemm_mma<1, 1><<<dim3(1, 64), blk, SMEM>>>(xr, wk, bk, kp, NTOK, HDIM, CDIM, 1.0f);
    // vT = Wv @ x.T + bv[m] : M=1024 (channels), N=8192 (tokens), K=1024
    gemm_mma<2, 1><<<dim3(64, 8), blk, SMEM>>>(wv, xr, bv, vTp, CDIM, NTOK, CDIM, 1.0f);

    // scores = (q @ k.T) * scale : M=N=8192, K=128
    gemm_mma<0, 0><<<dim3(64, 64), blk, SMEM>>>(qp, kp, nullptr, sp, NTOK, NTOK, HDIM, scale);

    softmax_rows<<<NTOK, blk>>>(sp);

    // o = attn @ vT.T : M=8192, N=1024, K=8192  (output tf32-rounded)
    gemm_mma<0, 1><<<dim3(8, 64), blk, SMEM>>>(sp, vTp, nullptr, op, NTOK, CDIM, NTOK, 1.0f);

    // out = o @ Wo.T + bo : M=8192, N=1024, K=1024
    gemm_mma<1, 0><<<dim3(8, 64), blk, SMEM>>>(op, wo, bo, out, NTOK, CDIM, CDIM, 1.0f);
}